// round 9
// baseline (speedup 1.0000x reference)
#include <cuda_runtime.h>
#include <cuda_fp16.h>
#include <cstdint>

#define NN      50000
#define NE      400000
#define NG      128
#define IN_DIM  768
#define HID     128
#define NCLS    11
#define BN_EPS  1e-5f

#define WOFF1   0
#define WOFF2   (256 * IN_DIM)
#define WOFF3   (256 * IN_DIM + 256 * HID)
#define WTOT    (256 * (IN_DIM + 2 * HID))

// ---------------- scratch (device globals; no allocation allowed) ----------------
__device__ __align__(16) __half g_yagg[(size_t)NN * 128];    // agg-side GEMM out (fp16)
__device__ __align__(16) float  g_yself[(size_t)NN * 128];   // self-side GEMM out (fp32)
__device__ float    g_hpre[(size_t)NN * HID];                // pre-BN activations
__device__ __align__(16) __half g_af16[(size_t)NN * IN_DIM]; // activations, fp16
__device__ __align__(16) __half g_wh[WTOT];                  // all layers' [Wl;Wr] fp16 hi
__device__ __align__(16) __half g_wl[WTOT];                  // all layers' [Wl;Wr] fp16 lo
__device__ int      g_deg[NN];
__device__ int      g_start[NN];
__device__ int      g_cursor[NN];
__device__ int      g_total;
__device__ int      g_csr[NE];
__device__ float    g_stats[256];               // [0:128)=sum, [128:256)=sumsq
__device__ float    g_coef[256];                // [0:128)=scale, [128:256)=shift
__device__ unsigned g_pool[NG * HID];           // order-preserving-encoded max

// ---------------- helpers ----------------
__device__ __forceinline__ uint32_t smem_u32(const void* p) {
    uint32_t a;
    asm("{ .reg .u64 t; cvta.to.shared.u64 t, %1; cvt.u32.u64 %0, t; }" : "=r"(a) : "l"(p));
    return a;
}
__device__ __forceinline__ unsigned fenc(float f) {
    unsigned u = __float_as_uint(f);
    return (u >> 31) ? ~u : (u | 0x80000000u);
}
__device__ __forceinline__ float fdec(unsigned e) {
    return (e >> 31) ? __uint_as_float(e & 0x7fffffffu) : __uint_as_float(~e);
}

#define LDMX4(d, a)                                                                  \
    asm volatile("ldmatrix.sync.aligned.m8n8.x4.shared.b16 {%0,%1,%2,%3}, [%4];"     \
        : "=r"((d)[0]), "=r"((d)[1]), "=r"((d)[2]), "=r"((d)[3]) : "r"(a))

#define CPASYNC16(dst, src) \
    asm volatile("cp.async.cg.shared.global [%0], [%1], 16;" :: "r"(dst), "l"(src) : "memory")
#define CPASYNC16Z(dst, src, sz) \
    asm volatile("cp.async.cg.shared.global [%0], [%1], 16, %2;" :: "r"(dst), "l"(src), "r"(sz) : "memory")
#define CPCOMMIT() asm volatile("cp.async.commit_group;" ::: "memory")
#define CPWAIT0()  asm volatile("cp.async.wait_group 0;" ::: "memory")

__device__ __forceinline__ void mma16816(float* c, const uint32_t* a, const uint32_t* b) {
    asm volatile(
        "mma.sync.aligned.m16n8k16.row.col.f32.f16.f16.f32 "
        "{%0,%1,%2,%3}, {%4,%5,%6,%7}, {%8,%9}, {%0,%1,%2,%3};"
        : "+f"(c[0]), "+f"(c[1]), "+f"(c[2]), "+f"(c[3])
        : "r"(a[0]), "r"(a[1]), "r"(a[2]), "r"(a[3]), "r"(b[0]), "r"(b[1]));
}

// ---------------- CSR build ----------------
__global__ void zero_deg_k() {          // also zero pool maxima + stats
    int i = blockIdx.x * blockDim.x + threadIdx.x;
    if (i < NN) g_deg[i] = 0;
    if (i < NG * HID) g_pool[i] = 0x007fffffu;   // fenc(-inf)
    if (i < 256) g_stats[i] = 0.f;
    if (i == 0) g_total = 0;
}

__global__ void hist_k(const int* __restrict__ dst) {
    int e = blockIdx.x * blockDim.x + threadIdx.x;
    if (e < NE) atomicAdd(&g_deg[dst[e]], 1);
}

__global__ void alloc_off_k() {
    int i = blockIdx.x * blockDim.x + threadIdx.x;
    int lane = threadIdx.x & 31;
    int d = (i < NN) ? g_deg[i] : 0;
    int inc = d;
    #pragma unroll
    for (int s = 1; s < 32; s <<= 1) {
        int v = __shfl_up_sync(0xffffffffu, inc, s);
        if (lane >= s) inc += v;
    }
    int ex  = inc - d;
    int tot = __shfl_sync(0xffffffffu, inc, 31);
    int base = 0;
    if (lane == 31) base = atomicAdd(&g_total, tot);
    base = __shfl_sync(0xffffffffu, base, 31);
    if (i < NN) { g_start[i] = base + ex; g_cursor[i] = base + ex; }
}

__global__ void fill_k(const int* __restrict__ src, const int* __restrict__ dst) {
    int e = blockIdx.x * blockDim.x + threadIdx.x;
    if (e < NE) {
        int p = atomicAdd(&g_cursor[dst[e]], 1);
        g_csr[p] = src[e];
    }
}

// ---------------- conversions ----------------
// all three layers' fused [Wl;Wr] -> fp16 hi + fp16 residual, converted up front
__global__ void convert_w_all_k(const float* __restrict__ W1l, const float* __restrict__ W1r,
                                const float* __restrict__ W2l, const float* __restrict__ W2r,
                                const float* __restrict__ W3l, const float* __restrict__ W3r) {
    int idx = blockIdx.x * blockDim.x + threadIdx.x;
    if (idx >= WTOT) return;
    const float *Wl, *Wr;
    int K, local;
    if (idx < WOFF2)      { Wl = W1l; Wr = W1r; K = IN_DIM; local = idx; }
    else if (idx < WOFF3) { Wl = W2l; Wr = W2r; K = HID;    local = idx - WOFF2; }
    else                  { Wl = W3l; Wr = W3r; K = HID;    local = idx - WOFF3; }
    int row = local / K, col = local - row * K;
    float v = (row < 128) ? Wl[row * K + col] : Wr[(row - 128) * K + col];
    __half hi = __float2half(v);
    __half lo = __float2half(v - __half2float(hi));
    g_wh[idx] = hi;
    g_wl[idx] = lo;
}

__global__ void conv_x_k(const float* __restrict__ x) {
    size_t i = (size_t)(blockIdx.x * blockDim.x + threadIdx.x) * 4;
    if (i >= (size_t)NN * IN_DIM) return;
    float4 v = *reinterpret_cast<const float4*>(x + i);
    __half2 p0 = __floats2half2_rn(v.x, v.y);
    __half2 p1 = __floats2half2_rn(v.z, v.w);
    *reinterpret_cast<uint2*>(g_af16 + i) = make_uint2(*(uint32_t*)&p0, *(uint32_t*)&p1);
}

// ---------------- tensor-core GEMM (fp16 2-term: A*Wh + A*Wl) ----------------
// agg half (cols 0..127) stored fp16 to g_yagg, self half fp32 to g_yself.
#define PADK  40
#define ASUB  10240
#define BUFB  (3 * ASUB)
#define GEMM_SMEM (2 * BUFB)

#define HALF_TILE(KOFF)                                                              \
    do {                                                                             \
        uint32_t ah[2][4];                                                           \
        LDMX4(ah[0], pA + (KOFF));                                                   \
        LDMX4(ah[1], pA + (KOFF) + 16 * PADK * 2);                                   \
        _Pragma("unroll")                                                            \
        for (int p = 0; p < 4; p++) {                                                \
            uint32_t bh[4], bl[4];                                                   \
            LDMX4(bh, pWh + (KOFF) + (uint32_t)(p * 16 * PADK * 2));                 \
            LDMX4(bl, pWl + (KOFF) + (uint32_t)(p * 16 * PADK * 2));                 \
            const int n0 = 2 * p, n1 = 2 * p + 1;                                    \
            mma16816(acc[0][n0], ah[0], bh);                                         \
            mma16816(acc[1][n0], ah[1], bh);                                         \
            mma16816(acc[0][n1], ah[0], bh + 2);                                     \
            mma16816(acc[1][n1], ah[1], bh + 2);                                     \
            mma16816(acc[0][n0], ah[0], bl);                                         \
            mma16816(acc[1][n0], ah[1], bl);                                         \
            mma16816(acc[0][n1], ah[0], bl + 2);                                     \
            mma16816(acc[1][n1], ah[1], bl + 2);                                     \
        }                                                                            \
    } while (0)

__global__ __launch_bounds__(256, 2)
void gemm_mma(int M, int K, int woff) {
    extern __shared__ char dsm[];
    const uint32_t sm0 = smem_u32(dsm);

    const int tid  = threadIdx.x;
    const int lane = tid & 31;
    const int wid  = tid >> 5;
    const int wm   = wid & 3;
    const int wn   = wid >> 2;
    const int row0 = (blockIdx.x >> 1) * 128;
    const int n0g  = (blockIdx.x & 1) * 128;

    const int a_row = lane & 15;
    const int a_kh  = (lane >> 4) * 8;
    const uint32_t aoff = (uint32_t)(((wm * 32 + a_row) * PADK + a_kh) * 2);
    const int b_row = ((lane >> 4) << 3) + (lane & 7);
    const int b_kh  = ((lane >> 3) & 1) * 8;
    const uint32_t boff = (uint32_t)(((wn * 64 + b_row) * PADK + b_kh) * 2);

    float acc[2][8][4];
    #pragma unroll
    for (int i = 0; i < 2; i++)
        #pragma unroll
        for (int j = 0; j < 8; j++)
            #pragma unroll
            for (int q = 0; q < 4; q++) acc[i][j][q] = 0.f;

    const int ntiles = K / 32;
    const __half* wh = g_wh + woff;
    const __half* wl = g_wl + woff;

    auto fill = [&](int t) {
        const int k0 = t * 32;
        const uint32_t base = sm0 + (uint32_t)(t & 1) * BUFB;
        #pragma unroll
        for (int i = 0; i < 2; i++) {
            int s   = tid + 256 * i;
            int r   = s >> 2;
            int seg = s & 3;
            uint32_t off = (uint32_t)(r * (PADK * 2) + seg * 16);
            size_t go = (size_t)(row0 + r) * K + k0 + seg * 8;
            int sz = (row0 + r < M) ? 16 : 0;
            CPASYNC16Z(base + off, (const void*)(g_af16 + go), sz);
        }
        #pragma unroll
        for (int i = 0; i < 2; i++) {
            int s   = tid + 256 * i;
            int r   = s >> 2;
            int seg = s & 3;
            uint32_t off = (uint32_t)(r * (PADK * 2) + seg * 16);
            size_t go = (size_t)(n0g + r) * K + k0 + seg * 8;
            CPASYNC16(base + ASUB + off,     (const void*)(wh + go));
            CPASYNC16(base + 2 * ASUB + off, (const void*)(wl + go));
        }
        CPCOMMIT();
    };

    fill(0);
    for (int t = 0; t < ntiles; t++) {
        CPWAIT0();
        __syncthreads();

        const uint32_t base = sm0 + (uint32_t)(t & 1) * BUFB;
        const uint32_t pA  = base + aoff;
        const uint32_t pWh = base + ASUB + boff;
        const uint32_t pWl = base + 2 * ASUB + boff;

        if (t + 1 < ntiles) fill(t + 1);

        HALF_TILE(0u);
        HALF_TILE(32u);
    }

    // ---- store C: agg half -> fp16, self half -> fp32 ----
    const int g   = lane >> 2;
    const int tig = lane & 3;
    if (n0g == 0) {
        #pragma unroll
        for (int mt = 0; mt < 2; mt++) {
            #pragma unroll
            for (int nt = 0; nt < 8; nt++) {
                int r = row0 + wm * 32 + mt * 16 + g;
                int c = wn * 64 + nt * 8 + 2 * tig;
                if (r < M) {
                    __half2 h = __floats2half2_rn(acc[mt][nt][0], acc[mt][nt][1]);
                    *reinterpret_cast<__half2*>(&g_yagg[(size_t)r * 128 + c]) = h;
                }
                if (r + 8 < M) {
                    __half2 h = __floats2half2_rn(acc[mt][nt][2], acc[mt][nt][3]);
                    *reinterpret_cast<__half2*>(&g_yagg[(size_t)(r + 8) * 128 + c]) = h;
                }
            }
        }
    } else {
        #pragma unroll
        for (int mt = 0; mt < 2; mt++) {
            #pragma unroll
            for (int nt = 0; nt < 8; nt++) {
                int r = row0 + wm * 32 + mt * 16 + g;
                int c = wn * 64 + nt * 8 + 2 * tig;
                if (r < M)
                    *reinterpret_cast<float2*>(&g_yself[(size_t)r * 128 + c]) =
                        make_float2(acc[mt][nt][0], acc[mt][nt][1]);
                if (r + 8 < M)
                    *reinterpret_cast<float2*>(&g_yself[(size_t)(r + 8) * 128 + c]) =
                        make_float2(acc[mt][nt][2], acc[mt][nt][3]);
            }
        }
    }
}

// ---------------- gather + combine + fused BN partial stats ----------------
// 8 warps/block, warp = one node. Block tree-reduces per-warp (sum, sumsq)
// slices and issues 256 spread atomicAdds.
__global__ void gather_bn_k(const float* __restrict__ bias) {
    __shared__ float sred[8][256];
    const int tid  = threadIdx.x;
    const int wid  = tid >> 5;
    const int lane = tid & 31;
    const int node = blockIdx.x * 8 + wid;     // 6250 * 8 == NN exactly

    int e0 = g_start[node];
    int deg = g_deg[node];
    int e1 = e0 + deg;
    float4 a0 = make_float4(0.f, 0.f, 0.f, 0.f);
    float4 a1 = make_float4(0.f, 0.f, 0.f, 0.f);
    float4 a2 = make_float4(0.f, 0.f, 0.f, 0.f);
    float4 a3 = make_float4(0.f, 0.f, 0.f, 0.f);

    auto addrow = [&](float4& a, int s) {
        uint2 u = *reinterpret_cast<const uint2*>(g_yagg + (size_t)s * 128 + lane * 4);
        float2 f0 = __half22float2(*reinterpret_cast<__half2*>(&u.x));
        float2 f1 = __half22float2(*reinterpret_cast<__half2*>(&u.y));
        a.x += f0.x; a.y += f0.y; a.z += f1.x; a.w += f1.y;
    };

    int e = e0;
    for (; e + 4 <= e1; e += 4) {
        int s0 = g_csr[e], s1 = g_csr[e + 1], s2 = g_csr[e + 2], s3 = g_csr[e + 3];
        addrow(a0, s0); addrow(a1, s1); addrow(a2, s2); addrow(a3, s3);
    }
    for (; e < e1; e++) addrow(a0, g_csr[e]);

    float4 acc;
    acc.x = (a0.x + a1.x) + (a2.x + a3.x);
    acc.y = (a0.y + a1.y) + (a2.y + a3.y);
    acc.z = (a0.z + a1.z) + (a2.z + a3.z);
    acc.w = (a0.w + a1.w) + (a2.w + a3.w);
    float invd = 1.f / fmaxf((float)deg, 1.f);
    float4 r  = *reinterpret_cast<const float4*>(g_yself + (size_t)node * 128 + lane * 4);
    float4 b4 = reinterpret_cast<const float4*>(bias)[lane];
    float4 o;
    o.x = acc.x * invd + r.x + b4.x;
    o.y = acc.y * invd + r.y + b4.y;
    o.z = acc.z * invd + r.z + b4.z;
    o.w = acc.w * invd + r.w + b4.w;
    *reinterpret_cast<float4*>(g_hpre + (size_t)node * HID + lane * 4) = o;

    // per-warp stats slices
    sred[wid][lane * 4 + 0] = o.x;
    sred[wid][lane * 4 + 1] = o.y;
    sred[wid][lane * 4 + 2] = o.z;
    sred[wid][lane * 4 + 3] = o.w;
    sred[wid][128 + lane * 4 + 0] = o.x * o.x;
    sred[wid][128 + lane * 4 + 1] = o.y * o.y;
    sred[wid][128 + lane * 4 + 2] = o.z * o.z;
    sred[wid][128 + lane * 4 + 3] = o.w * o.w;
    __syncthreads();

    float s = sred[0][tid] + sred[1][tid] + sred[2][tid] + sred[3][tid]
            + sred[4][tid] + sred[5][tid] + sred[6][tid] + sred[7][tid];
    atomicAdd(&g_stats[tid], s);
}

// ---------------- BN coef: stats -> scale/shift, then self-zero stats ----------------
__global__ void coef_k(const float* __restrict__ gamma, const float* __restrict__ beta) {
    int f = threadIdx.x;  // 128
    float s  = g_stats[f];
    float s2 = g_stats[f + 128];
    float mean = s * (1.f / NN);
    float var  = s2 * (1.f / NN) - mean * mean;
    float rstd = rsqrtf(var + BN_EPS);
    float g = gamma[f] * rstd;
    g_coef[f]       = g;
    g_coef[f + 128] = beta[f] - mean * g;
    g_stats[f]       = 0.f;
    g_stats[f + 128] = 0.f;
}

// relu + write fp16 (feeds next GEMM)
__global__ void bn_norm_k() {
    int f = threadIdx.x;
    float g = g_coef[f];
    float b = g_coef[f + 128];
    for (int r = blockIdx.x; r < NN; r += gridDim.x) {
        float v = fmaxf(g_hpre[(size_t)r * HID + f] * g + b, 0.f);
        g_af16[(size_t)r * HID + f] = __float2half(v);
    }
}

// ---------------- fused BN3 + global max pool (batch is sorted) ----------------
#define POOL_CHUNK 512
__global__ void bn_pool_k(const int* __restrict__ batch) {
    int f = threadIdx.x;  // 128
    float g = g_coef[f];
    float b = g_coef[f + 128];
    int r0 = blockIdx.x * POOL_CHUNK;
    int r1 = min(r0 + POOL_CHUNK, NN);
    int cur = -1;
    float m = -3.4e38f;
    for (int r = r0; r < r1; r++) {
        int gi = batch[r];
        if (gi != cur) {
            if (cur >= 0) atomicMax(&g_pool[cur * HID + f], fenc(m));
            cur = gi;
            m = -3.4e38f;
        }
        m = fmaxf(m, g_hpre[(size_t)r * HID + f] * g + b);
    }
    if (cur >= 0) atomicMax(&g_pool[cur * HID + f], fenc(m));
}

// ---------------- final linear ----------------
__global__ void final_linear_k(const float* __restrict__ Wlin, const float* __restrict__ blin,
                               float* __restrict__ out) {
    __shared__ float sh[HID];
    int g = blockIdx.x, t = threadIdx.x;
    sh[t] = fdec(g_pool[g * HID + t]);
    __syncthreads();
    if (t < NCLS) {
        float a = blin[t];
        #pragma unroll 8
        for (int k = 0; k < HID; k++) a += sh[k] * Wlin[t * HID + k];
        out[g * NCLS + t] = a;
    }
}

// ---------------- launch ----------------
extern "C" void kernel_launch(void* const* d_in, const int* in_sizes, int n_in,
                              void* d_out, int out_size) {
    const float* x    = (const float*)d_in[0];
    const int*   src  = (const int*)d_in[1];
    const int*   dst  = src + NE;
    const int*   batch = (const int*)d_in[2];
    const float* W1l = (const float*)d_in[3];
    const float* b1  = (const float*)d_in[4];
    const float* W1r = (const float*)d_in[5];
    const float* g1  = (const float*)d_in[6];
    const float* be1 = (const float*)d_in[7];
    const float* W2l = (const float*)d_in[8];
    const float* b2  = (const float*)d_in[9];
    const float* W2r = (const float*)d_in[10];
    const float* g2  = (const float*)d_in[11];
    const float* be2 = (const float*)d_in[12];
    const float* W3l = (const float*)d_in[13];
    const float* b3  = (const float*)d_in[14];
    const float* W3r = (const float*)d_in[15];
    const float* g3  = (const float*)d_in[16];
    const float* be3 = (const float*)d_in[17];
    const float* Wlin = (const float*)d_in[18];
    const float* blin = (const float*)d_in[19];
    float* out = (float*)d_out;

    cudaFuncSetAttribute(gemm_mma, cudaFuncAttributeMaxDynamicSharedMemorySize, GEMM_SMEM);

    const int mblocks = (NN + 127) / 128;          // 391
    const int gblocks = mblocks * 2;
    const int gatherb = NN / 8;                    // 6250

    // ----- prologue + layer-1 GEMM (ncu capture slot = 4th launch) -----
    convert_w_all_k<<<(WTOT + 255) / 256, 256>>>(W1l, W1r, W2l, W2r, W3l, W3r);
    conv_x_k<<<(NN * IN_DIM / 4 + 255) / 256, 256>>>(x);
    zero_deg_k<<<(NN + 255) / 256, 256>>>();
    gemm_mma<<<gblocks, 256, GEMM_SMEM>>>(NN, IN_DIM, WOFF1);                // profiled

    // CSR build
    hist_k<<<(NE + 255) / 256, 256>>>(dst);
    alloc_off_k<<<(NN + 255) / 256, 256>>>();
    fill_k<<<(NE + 255) / 256, 256>>>(src, dst);

    // ----- layer 1 tail -----
    gather_bn_k<<<gatherb, 256>>>(b1);
    coef_k<<<1, 128>>>(g1, be1);
    bn_norm_k<<<512, 128>>>();

    // ----- layer 2 -----
    gemm_mma<<<gblocks, 256, GEMM_SMEM>>>(NN, HID, WOFF2);
    gather_bn_k<<<gatherb, 256>>>(b2);
    coef_k<<<1, 128>>>(g2, be2);
    bn_norm_k<<<512, 128>>>();

    // ----- layer 3 -----
    gemm_mma<<<gblocks, 256, GEMM_SMEM>>>(NN, HID, WOFF3);
    gather_bn_k<<<gatherb, 256>>>(b3);
    coef_k<<<1, 128>>>(g3, be3);
    bn_pool_k<<<(NN + POOL_CHUNK - 1) / POOL_CHUNK, 128>>>(batch);

    // ----- head -----
    final_linear_k<<<NG, HID>>>(Wlin, blin, out);
}

// round 12
// speedup vs baseline: 1.3850x; 1.3850x over previous
#include <cuda_runtime.h>
#include <cuda_fp16.h>
#include <cstdint>

#define NN      50000
#define NE      400000
#define NG      128
#define IN_DIM  768
#define HID     128
#define NCLS    11
#define BN_EPS  1e-5f

#define WOFF1   0
#define WOFF2   (256 * IN_DIM)
#define WOFF3   (256 * IN_DIM + 256 * HID)
#define WTOT    (256 * (IN_DIM + 2 * HID))

// ---------------- scratch (device globals; no allocation allowed) ----------------
__device__ __align__(16) __half g_yagg[(size_t)NN * 128];    // agg-side GEMM out (fp16)
__device__ __align__(16) float  g_yself[(size_t)NN * 128];   // self-side GEMM out (fp32)
__device__ float    g_hpre[(size_t)NN * HID];                // pre-BN activations
__device__ __align__(16) __half g_af16[(size_t)NN * IN_DIM]; // activations, fp16
__device__ __align__(16) __half g_wh[WTOT];                  // all layers' [Wl;Wr] fp16
__device__ int      g_deg[NN];
__device__ int      g_start[NN];
__device__ int      g_cursor[NN];
__device__ int      g_total;
__device__ int      g_csr[NE];
__device__ float    g_stats[256];               // [0:128)=sum, [128:256)=sumsq
__device__ float    g_coef[256];                // [0:128)=scale, [128:256)=shift
__device__ unsigned g_pool[NG * HID];           // order-preserving-encoded max

// ---------------- helpers ----------------
__device__ __forceinline__ uint32_t smem_u32(const void* p) {
    uint32_t a;
    asm("{ .reg .u64 t; cvta.to.shared.u64 t, %1; cvt.u32.u64 %0, t; }" : "=r"(a) : "l"(p));
    return a;
}
__device__ __forceinline__ unsigned fenc(float f) {
    unsigned u = __float_as_uint(f);
    return (u >> 31) ? ~u : (u | 0x80000000u);
}
__device__ __forceinline__ float fdec(unsigned e) {
    return (e >> 31) ? __uint_as_float(e & 0x7fffffffu) : __uint_as_float(~e);
}

#define LDMX4(d, a)                                                                  \
    asm volatile("ldmatrix.sync.aligned.m8n8.x4.shared.b16 {%0,%1,%2,%3}, [%4];"     \
        : "=r"((d)[0]), "=r"((d)[1]), "=r"((d)[2]), "=r"((d)[3]) : "r"(a))

#define CPASYNC16(dst, src) \
    asm volatile("cp.async.cg.shared.global [%0], [%1], 16;" :: "r"(dst), "l"(src) : "memory")
#define CPASYNC16Z(dst, src, sz) \
    asm volatile("cp.async.cg.shared.global [%0], [%1], 16, %2;" :: "r"(dst), "l"(src), "r"(sz) : "memory")
#define CPCOMMIT() asm volatile("cp.async.commit_group;" ::: "memory")
#define CPWAIT0()  asm volatile("cp.async.wait_group 0;" ::: "memory")

__device__ __forceinline__ void mma16816(float* c, const uint32_t* a, const uint32_t* b) {
    asm volatile(
        "mma.sync.aligned.m16n8k16.row.col.f32.f16.f16.f32 "
        "{%0,%1,%2,%3}, {%4,%5,%6,%7}, {%8,%9}, {%0,%1,%2,%3};"
        : "+f"(c[0]), "+f"(c[1]), "+f"(c[2]), "+f"(c[3])
        : "r"(a[0]), "r"(a[1]), "r"(a[2]), "r"(a[3]), "r"(b[0]), "r"(b[1]));
}

// ---------------- CSR build ----------------
__global__ void zero_deg_k() {          // also zero pool maxima + stats
    int i = blockIdx.x * blockDim.x + threadIdx.x;
    if (i < NN) g_deg[i] = 0;
    if (i < NG * HID) g_pool[i] = 0x007fffffu;   // fenc(-inf)
    if (i < 256) g_stats[i] = 0.f;
    if (i == 0) g_total = 0;
}

__global__ void hist_k(const int* __restrict__ dst) {
    int e = blockIdx.x * blockDim.x + threadIdx.x;
    if (e < NE) atomicAdd(&g_deg[dst[e]], 1);
}

__global__ void alloc_off_k() {
    int i = blockIdx.x * blockDim.x + threadIdx.x;
    int lane = threadIdx.x & 31;
    int d = (i < NN) ? g_deg[i] : 0;
    int inc = d;
    #pragma unroll
    for (int s = 1; s < 32; s <<= 1) {
        int v = __shfl_up_sync(0xffffffffu, inc, s);
        if (lane >= s) inc += v;
    }
    int ex  = inc - d;
    int tot = __shfl_sync(0xffffffffu, inc, 31);
    int base = 0;
    if (lane == 31) base = atomicAdd(&g_total, tot);
    base = __shfl_sync(0xffffffffu, base, 31);
    if (i < NN) { g_start[i] = base + ex; g_cursor[i] = base + ex; }
}

__global__ void fill_k(const int* __restrict__ src, const int* __restrict__ dst) {
    int e = blockIdx.x * blockDim.x + threadIdx.x;
    if (e < NE) {
        int p = atomicAdd(&g_cursor[dst[e]], 1);
        g_csr[p] = src[e];
    }
}

// ---------------- conversions ----------------
__global__ void convert_w_all_k(const float* __restrict__ W1l, const float* __restrict__ W1r,
                                const float* __restrict__ W2l, const float* __restrict__ W2r,
                                const float* __restrict__ W3l, const float* __restrict__ W3r) {
    int idx = blockIdx.x * blockDim.x + threadIdx.x;
    if (idx >= WTOT) return;
    const float *Wl, *Wr;
    int K, local;
    if (idx < WOFF2)      { Wl = W1l; Wr = W1r; K = IN_DIM; local = idx; }
    else if (idx < WOFF3) { Wl = W2l; Wr = W2r; K = HID;    local = idx - WOFF2; }
    else                  { Wl = W3l; Wr = W3r; K = HID;    local = idx - WOFF3; }
    int row = local / K, col = local - row * K;
    float v = (row < 128) ? Wl[row * K + col] : Wr[(row - 128) * K + col];
    g_wh[idx] = __float2half(v);
}

__global__ void conv_x_k(const float* __restrict__ x) {
    size_t i = (size_t)(blockIdx.x * blockDim.x + threadIdx.x) * 4;
    if (i >= (size_t)NN * IN_DIM) return;
    float4 v = *reinterpret_cast<const float4*>(x + i);
    __half2 p0 = __floats2half2_rn(v.x, v.y);
    __half2 p1 = __floats2half2_rn(v.z, v.w);
    *reinterpret_cast<uint2*>(g_af16 + i) = make_uint2(*(uint32_t*)&p0, *(uint32_t*)&p1);
}

// ---------------- tensor-core GEMM (single-term fp16: A * W) ----------------
// agg half (cols 0..127) stored fp16 to g_yagg, self half fp32 to g_yself.
#define PADK  40
#define ASUB  10240
#define BUFB  (2 * ASUB)            // A, W
#define GEMM_SMEM (2 * BUFB)

#define HALF_TILE(KOFF)                                                              \
    do {                                                                             \
        uint32_t ah[2][4];                                                           \
        LDMX4(ah[0], pA + (KOFF));                                                   \
        LDMX4(ah[1], pA + (KOFF) + 16 * PADK * 2);                                   \
        _Pragma("unroll")                                                            \
        for (int p = 0; p < 4; p++) {                                                \
            uint32_t bh[4];                                                          \
            LDMX4(bh, pWh + (KOFF) + (uint32_t)(p * 16 * PADK * 2));                 \
            const int n0 = 2 * p, n1 = 2 * p + 1;                                    \
            mma16816(acc[0][n0], ah[0], bh);                                         \
            mma16816(acc[1][n0], ah[1], bh);                                         \
            mma16816(acc[0][n1], ah[0], bh + 2);                                     \
            mma16816(acc[1][n1], ah[1], bh + 2);                                     \
        }                                                                            \
    } while (0)

__global__ __launch_bounds__(256, 2)
void gemm_mma(int M, int K, int woff) {
    extern __shared__ char dsm[];
    const uint32_t sm0 = smem_u32(dsm);

    const int tid  = threadIdx.x;
    const int lane = tid & 31;
    const int wid  = tid >> 5;
    const int wm   = wid & 3;
    const int wn   = wid >> 2;
    const int row0 = (blockIdx.x >> 1) * 128;
    const int n0g  = (blockIdx.x & 1) * 128;

    const int a_row = lane & 15;
    const int a_kh  = (lane >> 4) * 8;
    const uint32_t aoff = (uint32_t)(((wm * 32 + a_row) * PADK + a_kh) * 2);
    const int b_row = ((lane >> 4) << 3) + (lane & 7);
    const int b_kh  = ((lane >> 3) & 1) * 8;
    const uint32_t boff = (uint32_t)(((wn * 64 + b_row) * PADK + b_kh) * 2);

    float acc[2][8][4];
    #pragma unroll
    for (int i = 0; i < 2; i++)
        #pragma unroll
        for (int j = 0; j < 8; j++)
            #pragma unroll
            for (int q = 0; q < 4; q++) acc[i][j][q] = 0.f;

    const int ntiles = K / 32;
    const __half* wh = g_wh + woff;

    auto fill = [&](int t) {
        const int k0 = t * 32;
        const uint32_t base = sm0 + (uint32_t)(t & 1) * BUFB;
        #pragma unroll
        for (int i = 0; i < 2; i++) {
            int s   = tid + 256 * i;
            int r   = s >> 2;
            int seg = s & 3;
            uint32_t off = (uint32_t)(r * (PADK * 2) + seg * 16);
            size_t go = (size_t)(row0 + r) * K + k0 + seg * 8;
            int sz = (row0 + r < M) ? 16 : 0;
            CPASYNC16Z(base + off, (const void*)(g_af16 + go), sz);
        }
        #pragma unroll
        for (int i = 0; i < 2; i++) {
            int s   = tid + 256 * i;
            int r   = s >> 2;
            int seg = s & 3;
            uint32_t off = (uint32_t)(r * (PADK * 2) + seg * 16);
            size_t go = (size_t)(n0g + r) * K + k0 + seg * 8;
            CPASYNC16(base + ASUB + off, (const void*)(wh + go));
        }
        CPCOMMIT();
    };

    fill(0);
    for (int t = 0; t < ntiles; t++) {
        CPWAIT0();
        __syncthreads();

        const uint32_t base = sm0 + (uint32_t)(t & 1) * BUFB;
        const uint32_t pA  = base + aoff;
        const uint32_t pWh = base + ASUB + boff;

        if (t + 1 < ntiles) fill(t + 1);

        HALF_TILE(0u);
        HALF_TILE(32u);
    }

    // ---- store C: agg half -> fp16, self half -> fp32 ----
    const int g   = lane >> 2;
    const int tig = lane & 3;
    if (n0g == 0) {
        #pragma unroll
        for (int mt = 0; mt < 2; mt++) {
            #pragma unroll
            for (int nt = 0; nt < 8; nt++) {
                int r = row0 + wm * 32 + mt * 16 + g;
                int c = wn * 64 + nt * 8 + 2 * tig;
                if (r < M) {
                    __half2 h = __floats2half2_rn(acc[mt][nt][0], acc[mt][nt][1]);
                    *reinterpret_cast<__half2*>(&g_yagg[(size_t)r * 128 + c]) = h;
                }
                if (r + 8 < M) {
                    __half2 h = __floats2half2_rn(acc[mt][nt][2], acc[mt][nt][3]);
                    *reinterpret_cast<__half2*>(&g_yagg[(size_t)(r + 8) * 128 + c]) = h;
                }
            }
        }
    } else {
        #pragma unroll
        for (int mt = 0; mt < 2; mt++) {
            #pragma unroll
            for (int nt = 0; nt < 8; nt++) {
                int r = row0 + wm * 32 + mt * 16 + g;
                int c = wn * 64 + nt * 8 + 2 * tig;
                if (r < M)
                    *reinterpret_cast<float2*>(&g_yself[(size_t)r * 128 + c]) =
                        make_float2(acc[mt][nt][0], acc[mt][nt][1]);
                if (r + 8 < M)
                    *reinterpret_cast<float2*>(&g_yself[(size_t)(r + 8) * 128 + c]) =
                        make_float2(acc[mt][nt][2], acc[mt][nt][3]);
            }
        }
    }
}

// ---------------- gather + combine (warp-independent, no syncs) ----------------
__global__ void gather_k(const float* __restrict__ bias) {
    int node = (blockIdx.x * blockDim.x + threadIdx.x) >> 5;
    int lane = threadIdx.x & 31;
    if (node >= NN) return;
    int e0 = g_start[node];
    int deg = g_deg[node];
    int e1 = e0 + deg;
    float4 a0 = make_float4(0.f, 0.f, 0.f, 0.f);
    float4 a1 = make_float4(0.f, 0.f, 0.f, 0.f);
    float4 a2 = make_float4(0.f, 0.f, 0.f, 0.f);
    float4 a3 = make_float4(0.f, 0.f, 0.f, 0.f);

    auto addrow = [&](float4& a, int s) {
        uint2 u = *reinterpret_cast<const uint2*>(g_yagg + (size_t)s * 128 + lane * 4);
        float2 f0 = __half22float2(*reinterpret_cast<__half2*>(&u.x));
        float2 f1 = __half22float2(*reinterpret_cast<__half2*>(&u.y));
        a.x += f0.x; a.y += f0.y; a.z += f1.x; a.w += f1.y;
    };

    int e = e0;
    for (; e + 4 <= e1; e += 4) {
        int s0 = g_csr[e], s1 = g_csr[e + 1], s2 = g_csr[e + 2], s3 = g_csr[e + 3];
        addrow(a0, s0); addrow(a1, s1); addrow(a2, s2); addrow(a3, s3);
    }
    for (; e < e1; e++) addrow(a0, g_csr[e]);

    float4 acc;
    acc.x = (a0.x + a1.x) + (a2.x + a3.x);
    acc.y = (a0.y + a1.y) + (a2.y + a3.y);
    acc.z = (a0.z + a1.z) + (a2.z + a3.z);
    acc.w = (a0.w + a1.w) + (a2.w + a3.w);
    float invd = 1.f / fmaxf((float)deg, 1.f);
    float4 r  = *reinterpret_cast<const float4*>(g_yself + (size_t)node * 128 + lane * 4);
    float4 b4 = reinterpret_cast<const float4*>(bias)[lane];
    float4 o;
    o.x = acc.x * invd + r.x + b4.x;
    o.y = acc.y * invd + r.y + b4.y;
    o.z = acc.z * invd + r.z + b4.z;
    o.w = acc.w * invd + r.w + b4.w;
    *reinterpret_cast<float4*>(g_hpre + (size_t)node * HID + lane * 4) = o;
}

// ---------------- BN stats (256 blocks, spread atomics) ----------------
__global__ void bn_stats_k() {
    int f = threadIdx.x;  // 128
    float s = 0.f, s2 = 0.f;
    for (int r = blockIdx.x; r < NN; r += 256) {
        float v = g_hpre[(size_t)r * HID + f];
        s += v; s2 += v * v;
    }
    atomicAdd(&g_stats[f], s);
    atomicAdd(&g_stats[f + 128], s2);
}

// stats -> scale/shift, then self-zero stats for the next layer
__global__ void coef_k(const float* __restrict__ gamma, const float* __restrict__ beta) {
    int f = threadIdx.x;  // 128
    float s  = g_stats[f];
    float s2 = g_stats[f + 128];
    float mean = s * (1.f / NN);
    float var  = s2 * (1.f / NN) - mean * mean;
    float rstd = rsqrtf(var + BN_EPS);
    float g = gamma[f] * rstd;
    g_coef[f]       = g;
    g_coef[f + 128] = beta[f] - mean * g;
    g_stats[f]       = 0.f;
    g_stats[f + 128] = 0.f;
}

// relu + write fp16 (feeds next GEMM)
__global__ void bn_norm_k() {
    int f = threadIdx.x;
    float g = g_coef[f];
    float b = g_coef[f + 128];
    for (int r = blockIdx.x; r < NN; r += gridDim.x) {
        float v = fmaxf(g_hpre[(size_t)r * HID + f] * g + b, 0.f);
        g_af16[(size_t)r * HID + f] = __float2half(v);
    }
}

// ---------------- fused BN3 + global max pool (batch is sorted) ----------------
#define POOL_CHUNK 512
__global__ void bn_pool_k(const int* __restrict__ batch) {
    int f = threadIdx.x;  // 128
    float g = g_coef[f];
    float b = g_coef[f + 128];
    int r0 = blockIdx.x * POOL_CHUNK;
    int r1 = min(r0 + POOL_CHUNK, NN);
    int cur = -1;
    float m = -3.4e38f;
    for (int r = r0; r < r1; r++) {
        int gi = batch[r];
        if (gi != cur) {
            if (cur >= 0) atomicMax(&g_pool[cur * HID + f], fenc(m));
            cur = gi;
            m = -3.4e38f;
        }
        m = fmaxf(m, g_hpre[(size_t)r * HID + f] * g + b);
    }
    if (cur >= 0) atomicMax(&g_pool[cur * HID + f], fenc(m));
}

// ---------------- final linear ----------------
__global__ void final_linear_k(const float* __restrict__ Wlin, const float* __restrict__ blin,
                               float* __restrict__ out) {
    __shared__ float sh[HID];
    int g = blockIdx.x, t = threadIdx.x;
    sh[t] = fdec(g_pool[g * HID + t]);
    __syncthreads();
    if (t < NCLS) {
        float a = blin[t];
        #pragma unroll 8
        for (int k = 0; k < HID; k++) a += sh[k] * Wlin[t * HID + k];
        out[g * NCLS + t] = a;
    }
}

// ---------------- launch ----------------
extern "C" void kernel_launch(void* const* d_in, const int* in_sizes, int n_in,
                              void* d_out, int out_size) {
    const float* x    = (const float*)d_in[0];
    const int*   src  = (const int*)d_in[1];
    const int*   dst  = src + NE;
    const int*   batch = (const int*)d_in[2];
    const float* W1l = (const float*)d_in[3];
    const float* b1  = (const float*)d_in[4];
    const float* W1r = (const float*)d_in[5];
    const float* g1  = (const float*)d_in[6];
    const float* be1 = (const float*)d_in[7];
    const float* W2l = (const float*)d_in[8];
    const float* b2  = (const float*)d_in[9];
    const float* W2r = (const float*)d_in[10];
    const float* g2  = (const float*)d_in[11];
    const float* be2 = (const float*)d_in[12];
    const float* W3l = (const float*)d_in[13];
    const float* b3  = (const float*)d_in[14];
    const float* W3r = (const float*)d_in[15];
    const float* g3  = (const float*)d_in[16];
    const float* be3 = (const float*)d_in[17];
    const float* Wlin = (const float*)d_in[18];
    const float* blin = (const float*)d_in[19];
    float* out = (float*)d_out;

    cudaFuncSetAttribute(gemm_mma, cudaFuncAttributeMaxDynamicSharedMemorySize, GEMM_SMEM);

    const int mblocks = (NN + 127) / 128;          // 391
    const int gblocks = mblocks * 2;
    const int gwarps  = (NN * 32 + 255) / 256;

    // ----- prologue + layer-1 GEMM (ncu capture slot = 4th launch) -----
    convert_w_all_k<<<(WTOT + 255) / 256, 256>>>(W1l, W1r, W2l, W2r, W3l, W3r);
    conv_x_k<<<(NN * IN_DIM / 4 + 255) / 256, 256>>>(x);
    zero_deg_k<<<(NN + 255) / 256, 256>>>();
    gemm_mma<<<gblocks, 256, GEMM_SMEM>>>(NN, IN_DIM, WOFF1);                // profiled

    // CSR build
    hist_k<<<(NE + 255) / 256, 256>>>(dst);
    alloc_off_k<<<(NN + 255) / 256, 256>>>();
    fill_k<<<(NE + 255) / 256, 256>>>(src, dst);

    // ----- layer 1 tail -----
    gather_k<<<gwarps, 256>>>(b1);
    bn_stats_k<<<256, 128>>>();
    coef_k<<<1, 128>>>(g1, be1);
    bn_norm_k<<<512, 128>>>();

    // ----- layer 2 -----
    gemm_mma<<<gblocks, 256, GEMM_SMEM>>>(NN, HID, WOFF2);
    gather_k<<<gwarps, 256>>>(b2);
    bn_stats_k<<<256, 128>>>();
    coef_k<<<1, 128>>>(g2, be2);
    bn_norm_k<<<512, 128>>>();

    // ----- layer 3 -----
    gemm_mma<<<gblocks, 256, GEMM_SMEM>>>(NN, HID, WOFF3);
    gather_k<<<gwarps, 256>>>(b3);
    bn_stats_k<<<256, 128>>>();
    coef_k<<<1, 128>>>(g3, be3);
    bn_pool_k<<<(NN + POOL_CHUNK - 1) / POOL_CHUNK, 128>>>(batch);

    // ----- head -----
    final_linear_k<<<NG, HID>>>(Wlin, blin, out);
}

// round 13
// speedup vs baseline: 1.4044x; 1.0140x over previous
#include <cuda_runtime.h>
#include <cuda_fp16.h>
#include <cstdint>

#define NN      50000
#define NE      400000
#define NG      128
#define IN_DIM  768
#define HID     128
#define NCLS    11
#define BN_EPS  1e-5f

#define WOFF1   0
#define WOFF2   (256 * IN_DIM)
#define WOFF3   (256 * IN_DIM + 256 * HID)
#define WTOT    (256 * (IN_DIM + 2 * HID))

// ---------------- scratch (device globals; no allocation allowed) ----------------
__device__ __align__(16) __half g_yagg[(size_t)NN * 128];    // agg-side GEMM out (fp16)
__device__ __align__(16) float  g_yself[(size_t)NN * 128];   // self-side GEMM out (fp32)
__device__ float    g_hpre[(size_t)NN * HID];                // pre-BN activations
__device__ __align__(16) __half g_af16[(size_t)NN * IN_DIM]; // activations, fp16
__device__ __align__(16) __half g_wh[WTOT];                  // all layers' [Wl;Wr] fp16
__device__ int      g_deg[NN];
__device__ int      g_start[NN];
__device__ int      g_cursor[NN];
__device__ int      g_total;
__device__ int      g_csr[NE];
__device__ float    g_stats[256];               // [0:128)=sum, [128:256)=sumsq
__device__ unsigned g_pool[NG * HID];           // order-preserving-encoded max

// ---------------- helpers ----------------
__device__ __forceinline__ uint32_t smem_u32(const void* p) {
    uint32_t a;
    asm("{ .reg .u64 t; cvta.to.shared.u64 t, %1; cvt.u32.u64 %0, t; }" : "=r"(a) : "l"(p));
    return a;
}
__device__ __forceinline__ unsigned fenc(float f) {
    unsigned u = __float_as_uint(f);
    return (u >> 31) ? ~u : (u | 0x80000000u);
}
__device__ __forceinline__ float fdec(unsigned e) {
    return (e >> 31) ? __uint_as_float(e & 0x7fffffffu) : __uint_as_float(~e);
}

#define LDMX4(d, a)                                                                  \
    asm volatile("ldmatrix.sync.aligned.m8n8.x4.shared.b16 {%0,%1,%2,%3}, [%4];"     \
        : "=r"((d)[0]), "=r"((d)[1]), "=r"((d)[2]), "=r"((d)[3]) : "r"(a))

#define CPASYNC16(dst, src) \
    asm volatile("cp.async.cg.shared.global [%0], [%1], 16;" :: "r"(dst), "l"(src) : "memory")
#define CPASYNC16Z(dst, src, sz) \
    asm volatile("cp.async.cg.shared.global [%0], [%1], 16, %2;" :: "r"(dst), "l"(src), "r"(sz) : "memory")
#define CPCOMMIT() asm volatile("cp.async.commit_group;" ::: "memory")
#define CPWAIT2()  asm volatile("cp.async.wait_group 2;" ::: "memory")

__device__ __forceinline__ void mma16816(float* c, const uint32_t* a, const uint32_t* b) {
    asm volatile(
        "mma.sync.aligned.m16n8k16.row.col.f32.f16.f16.f32 "
        "{%0,%1,%2,%3}, {%4,%5,%6,%7}, {%8,%9}, {%0,%1,%2,%3};"
        : "+f"(c[0]), "+f"(c[1]), "+f"(c[2]), "+f"(c[3])
        : "r"(a[0]), "r"(a[1]), "r"(a[2]), "r"(a[3]), "r"(b[0]), "r"(b[1]));
}

// ---------------- CSR build ----------------
__global__ void zero_deg_k() {          // also zero pool maxima + stats
    int i = blockIdx.x * blockDim.x + threadIdx.x;
    if (i < NN) g_deg[i] = 0;
    if (i < NG * HID) g_pool[i] = 0x007fffffu;   // fenc(-inf)
    if (i < 256) g_stats[i] = 0.f;
    if (i == 0) g_total = 0;
}

__global__ void hist_k(const int* __restrict__ dst) {
    int e = blockIdx.x * blockDim.x + threadIdx.x;
    if (e < NE) atomicAdd(&g_deg[dst[e]], 1);
}

__global__ void alloc_off_k() {
    int i = blockIdx.x * blockDim.x + threadIdx.x;
    int lane = threadIdx.x & 31;
    int d = (i < NN) ? g_deg[i] : 0;
    int inc = d;
    #pragma unroll
    for (int s = 1; s < 32; s <<= 1) {
        int v = __shfl_up_sync(0xffffffffu, inc, s);
        if (lane >= s) inc += v;
    }
    int ex  = inc - d;
    int tot = __shfl_sync(0xffffffffu, inc, 31);
    int base = 0;
    if (lane == 31) base = atomicAdd(&g_total, tot);
    base = __shfl_sync(0xffffffffu, base, 31);
    if (i < NN) { g_start[i] = base + ex; g_cursor[i] = base + ex; }
}

__global__ void fill_k(const int* __restrict__ src, const int* __restrict__ dst) {
    int e = blockIdx.x * blockDim.x + threadIdx.x;
    if (e < NE) {
        int p = atomicAdd(&g_cursor[dst[e]], 1);
        g_csr[p] = src[e];
    }
}

// ---------------- conversions ----------------
__global__ void convert_w_all_k(const float* __restrict__ W1l, const float* __restrict__ W1r,
                                const float* __restrict__ W2l, const float* __restrict__ W2r,
                                const float* __restrict__ W3l, const float* __restrict__ W3r) {
    int idx = blockIdx.x * blockDim.x + threadIdx.x;
    if (idx >= WTOT) return;
    const float *Wl, *Wr;
    int K, local;
    if (idx < WOFF2)      { Wl = W1l; Wr = W1r; K = IN_DIM; local = idx; }
    else if (idx < WOFF3) { Wl = W2l; Wr = W2r; K = HID;    local = idx - WOFF2; }
    else                  { Wl = W3l; Wr = W3r; K = HID;    local = idx - WOFF3; }
    int row = local / K, col = local - row * K;
    float v = (row < 128) ? Wl[row * K + col] : Wr[(row - 128) * K + col];
    g_wh[idx] = __float2half(v);
}

__global__ void conv_x_k(const float* __restrict__ x) {
    size_t i = (size_t)(blockIdx.x * blockDim.x + threadIdx.x) * 4;
    if (i >= (size_t)NN * IN_DIM) return;
    float4 v = *reinterpret_cast<const float4*>(x + i);
    __half2 p0 = __floats2half2_rn(v.x, v.y);
    __half2 p1 = __floats2half2_rn(v.z, v.w);
    *reinterpret_cast<uint2*>(g_af16 + i) = make_uint2(*(uint32_t*)&p0, *(uint32_t*)&p1);
}

// ---------------- tensor-core GEMM (single-term fp16, 4-stage pipeline) ----------------
#define PADK  40
#define ASUB  10240
#define BUFB  (2 * ASUB)            // A, W per stage
#define NSTAGE 4
#define GEMM_SMEM (NSTAGE * BUFB)   // 80 KB -> 2 CTAs/SM fits in 228 KB

#define HALF_TILE(KOFF)                                                              \
    do {                                                                             \
        uint32_t ah[2][4];                                                           \
        LDMX4(ah[0], pA + (KOFF));                                                   \
        LDMX4(ah[1], pA + (KOFF) + 16 * PADK * 2);                                   \
        _Pragma("unroll")                                                            \
        for (int p = 0; p < 4; p++) {                                                \
            uint32_t bh[4];                                                          \
            LDMX4(bh, pWh + (KOFF) + (uint32_t)(p * 16 * PADK * 2));                 \
            const int n0 = 2 * p, n1 = 2 * p + 1;                                    \
            mma16816(acc[0][n0], ah[0], bh);                                         \
            mma16816(acc[1][n0], ah[1], bh);                                         \
            mma16816(acc[0][n1], ah[0], bh + 2);                                     \
            mma16816(acc[1][n1], ah[1], bh + 2);                                     \
        }                                                                            \
    } while (0)

__global__ __launch_bounds__(256, 2)
void gemm_mma(int M, int K, int woff) {
    // block 0 re-zeroes BN stats for the upcoming layer (previous layer's
    // bn_norm has already consumed them; launch order makes this race-free)
    if (blockIdx.x == 0 && threadIdx.x < 256) g_stats[threadIdx.x] = 0.f;

    extern __shared__ char dsm[];
    const uint32_t sm0 = smem_u32(dsm);

    const int tid  = threadIdx.x;
    const int lane = tid & 31;
    const int wid  = tid >> 5;
    const int wm   = wid & 3;
    const int wn   = wid >> 2;
    const int row0 = (blockIdx.x >> 1) * 128;
    const int n0g  = (blockIdx.x & 1) * 128;

    const int a_row = lane & 15;
    const int a_kh  = (lane >> 4) * 8;
    const uint32_t aoff = (uint32_t)(((wm * 32 + a_row) * PADK + a_kh) * 2);
    const int b_row = ((lane >> 4) << 3) + (lane & 7);
    const int b_kh  = ((lane >> 3) & 1) * 8;
    const uint32_t boff = (uint32_t)(((wn * 64 + b_row) * PADK + b_kh) * 2);

    float acc[2][8][4];
    #pragma unroll
    for (int i = 0; i < 2; i++)
        #pragma unroll
        for (int j = 0; j < 8; j++)
            #pragma unroll
            for (int q = 0; q < 4; q++) acc[i][j][q] = 0.f;

    const int ntiles = K / 32;
    const __half* wh = g_wh + woff;

    auto fill = [&](int t) {
        if (t < ntiles) {
            const int k0 = t * 32;
            const uint32_t base = sm0 + (uint32_t)(t & (NSTAGE - 1)) * BUFB;
            #pragma unroll
            for (int i = 0; i < 2; i++) {
                int s   = tid + 256 * i;
                int r   = s >> 2;
                int seg = s & 3;
                uint32_t off = (uint32_t)(r * (PADK * 2) + seg * 16);
                size_t go = (size_t)(row0 + r) * K + k0 + seg * 8;
                int sz = (row0 + r < M) ? 16 : 0;
                CPASYNC16Z(base + off, (const void*)(g_af16 + go), sz);
            }
            #pragma unroll
            for (int i = 0; i < 2; i++) {
                int s   = tid + 256 * i;
                int r   = s >> 2;
                int seg = s & 3;
                uint32_t off = (uint32_t)(r * (PADK * 2) + seg * 16);
                size_t go = (size_t)(n0g + r) * K + k0 + seg * 8;
                CPASYNC16(base + ASUB + off, (const void*)(wh + go));
            }
        }
        CPCOMMIT();          // commit even when empty -> uniform group count
    };

    fill(0); fill(1); fill(2);
    for (int t = 0; t < ntiles; t++) {
        CPWAIT2();           // groups <= t+2 pending -> tile t landed
        __syncthreads();     // all warps done with compute(t-1); tile t visible

        const uint32_t base = sm0 + (uint32_t)(t & (NSTAGE - 1)) * BUFB;
        const uint32_t pA  = base + aoff;
        const uint32_t pWh = base + ASUB + boff;

        fill(t + 3);         // overwrites stage (t-1)&3 -- safe after the barrier

        HALF_TILE(0u);
        HALF_TILE(32u);
    }

    // ---- store C: agg half -> fp16, self half -> fp32 ----
    const int g   = lane >> 2;
    const int tig = lane & 3;
    if (n0g == 0) {
        #pragma unroll
        for (int mt = 0; mt < 2; mt++) {
            #pragma unroll
            for (int nt = 0; nt < 8; nt++) {
                int r = row0 + wm * 32 + mt * 16 + g;
                int c = wn * 64 + nt * 8 + 2 * tig;
                if (r < M) {
                    __half2 h = __floats2half2_rn(acc[mt][nt][0], acc[mt][nt][1]);
                    *reinterpret_cast<__half2*>(&g_yagg[(size_t)r * 128 + c]) = h;
                }
                if (r + 8 < M) {
                    __half2 h = __floats2half2_rn(acc[mt][nt][2], acc[mt][nt][3]);
                    *reinterpret_cast<__half2*>(&g_yagg[(size_t)(r + 8) * 128 + c]) = h;
                }
            }
        }
    } else {
        #pragma unroll
        for (int mt = 0; mt < 2; mt++) {
            #pragma unroll
            for (int nt = 0; nt < 8; nt++) {
                int r = row0 + wm * 32 + mt * 16 + g;
                int c = wn * 64 + nt * 8 + 2 * tig;
                if (r < M)
                    *reinterpret_cast<float2*>(&g_yself[(size_t)r * 128 + c]) =
                        make_float2(acc[mt][nt][0], acc[mt][nt][1]);
                if (r + 8 < M)
                    *reinterpret_cast<float2*>(&g_yself[(size_t)(r + 8) * 128 + c]) =
                        make_float2(acc[mt][nt][2], acc[mt][nt][3]);
            }
        }
    }
}

// ---------------- gather + combine (warp-independent, 8-deep MLP) ----------------
__global__ void gather_k(const float* __restrict__ bias) {
    int node = (blockIdx.x * blockDim.x + threadIdx.x) >> 5;
    int lane = threadIdx.x & 31;
    if (node >= NN) return;
    int e0 = g_start[node];
    int deg = g_deg[node];
    int e1 = e0 + deg;
    float4 a0 = make_float4(0.f, 0.f, 0.f, 0.f);
    float4 a1 = make_float4(0.f, 0.f, 0.f, 0.f);
    float4 a2 = make_float4(0.f, 0.f, 0.f, 0.f);
    float4 a3 = make_float4(0.f, 0.f, 0.f, 0.f);

    auto addrow = [&](float4& a, int s) {
        uint2 u = *reinterpret_cast<const uint2*>(g_yagg + (size_t)s * 128 + lane * 4);
        float2 f0 = __half22float2(*reinterpret_cast<__half2*>(&u.x));
        float2 f1 = __half22float2(*reinterpret_cast<__half2*>(&u.y));
        a.x += f0.x; a.y += f0.y; a.z += f1.x; a.w += f1.y;
    };

    int e = e0;
    for (; e + 8 <= e1; e += 8) {        // 8 independent row loads in flight
        int s0 = g_csr[e],     s1 = g_csr[e + 1], s2 = g_csr[e + 2], s3 = g_csr[e + 3];
        int s4 = g_csr[e + 4], s5 = g_csr[e + 5], s6 = g_csr[e + 6], s7 = g_csr[e + 7];
        addrow(a0, s0); addrow(a1, s1); addrow(a2, s2); addrow(a3, s3);
        addrow(a0, s4); addrow(a1, s5); addrow(a2, s6); addrow(a3, s7);
    }
    for (; e + 4 <= e1; e += 4) {
        int s0 = g_csr[e], s1 = g_csr[e + 1], s2 = g_csr[e + 2], s3 = g_csr[e + 3];
        addrow(a0, s0); addrow(a1, s1); addrow(a2, s2); addrow(a3, s3);
    }
    for (; e < e1; e++) addrow(a0, g_csr[e]);

    float4 acc;
    acc.x = (a0.x + a1.x) + (a2.x + a3.x);
    acc.y = (a0.y + a1.y) + (a2.y + a3.y);
    acc.z = (a0.z + a1.z) + (a2.z + a3.z);
    acc.w = (a0.w + a1.w) + (a2.w + a3.w);
    float invd = 1.f / fmaxf((float)deg, 1.f);
    float4 r  = *reinterpret_cast<const float4*>(g_yself + (size_t)node * 128 + lane * 4);
    float4 b4 = reinterpret_cast<const float4*>(bias)[lane];
    float4 o;
    o.x = acc.x * invd + r.x + b4.x;
    o.y = acc.y * invd + r.y + b4.y;
    o.z = acc.z * invd + r.z + b4.z;
    o.w = acc.w * invd + r.w + b4.w;
    *reinterpret_cast<float4*>(g_hpre + (size_t)node * HID + lane * 4) = o;
}

// ---------------- BN stats (256 blocks, spread atomics; stats pre-zeroed) ----------------
__global__ void bn_stats_k() {
    int f = threadIdx.x;  // 128
    float s = 0.f, s2 = 0.f;
    for (int r = blockIdx.x; r < NN; r += 256) {
        float v = g_hpre[(size_t)r * HID + f];
        s += v; s2 += v * v;
    }
    atomicAdd(&g_stats[f], s);
    atomicAdd(&g_stats[f + 128], s2);
}

// inline-coef BN: relu + write fp16 (feeds next GEMM)
__global__ void bn_norm_k(const float* __restrict__ gamma, const float* __restrict__ beta) {
    int f = threadIdx.x;
    float s  = g_stats[f];
    float s2 = g_stats[f + 128];
    float mean = s * (1.f / NN);
    float var  = s2 * (1.f / NN) - mean * mean;
    float rstd = rsqrtf(var + BN_EPS);
    float g = gamma[f] * rstd;
    float b = beta[f] - mean * g;
    for (int r = blockIdx.x; r < NN; r += gridDim.x) {
        float v = fmaxf(g_hpre[(size_t)r * HID + f] * g + b, 0.f);
        g_af16[(size_t)r * HID + f] = __float2half(v);
    }
}

// ---------------- fused BN3 (inline coef) + global max pool (batch sorted) ----------------
#define POOL_CHUNK 512
__global__ void bn_pool_k(const int* __restrict__ batch,
                          const float* __restrict__ gamma, const float* __restrict__ beta) {
    int f = threadIdx.x;  // 128
    float s  = g_stats[f];
    float s2 = g_stats[f + 128];
    float mean = s * (1.f / NN);
    float var  = s2 * (1.f / NN) - mean * mean;
    float rstd = rsqrtf(var + BN_EPS);
    float g = gamma[f] * rstd;
    float b = beta[f] - mean * g;
    int r0 = blockIdx.x * POOL_CHUNK;
    int r1 = min(r0 + POOL_CHUNK, NN);
    int cur = -1;
    float m = -3.4e38f;
    for (int r = r0; r < r1; r++) {
        int gi = batch[r];
        if (gi != cur) {
            if (cur >= 0) atomicMax(&g_pool[cur * HID + f], fenc(m));
            cur = gi;
            m = -3.4e38f;
        }
        m = fmaxf(m, g_hpre[(size_t)r * HID + f] * g + b);
    }
    if (cur >= 0) atomicMax(&g_pool[cur * HID + f], fenc(m));
}

// ---------------- final linear ----------------
__global__ void final_linear_k(const float* __restrict__ Wlin, const float* __restrict__ blin,
                               float* __restrict__ out) {
    __shared__ float sh[HID];
    int g = blockIdx.x, t = threadIdx.x;
    sh[t] = fdec(g_pool[g * HID + t]);
    __syncthreads();
    if (t < NCLS) {
        float a = blin[t];
        #pragma unroll 8
        for (int k = 0; k < HID; k++) a += sh[k] * Wlin[t * HID + k];
        out[g * NCLS + t] = a;
    }
}

// ---------------- launch ----------------
extern "C" void kernel_launch(void* const* d_in, const int* in_sizes, int n_in,
                              void* d_out, int out_size) {
    const float* x    = (const float*)d_in[0];
    const int*   src  = (const int*)d_in[1];
    const int*   dst  = src + NE;
    const int*   batch = (const int*)d_in[2];
    const float* W1l = (const float*)d_in[3];
    const float* b1  = (const float*)d_in[4];
    const float* W1r = (const float*)d_in[5];
    const float* g1  = (const float*)d_in[6];
    const float* be1 = (const float*)d_in[7];
    const float* W2l = (const float*)d_in[8];
    const float* b2  = (const float*)d_in[9];
    const float* W2r = (const float*)d_in[10];
    const float* g2  = (const float*)d_in[11];
    const float* be2 = (const float*)d_in[12];
    const float* W3l = (const float*)d_in[13];
    const float* b3  = (const float*)d_in[14];
    const float* W3r = (const float*)d_in[15];
    const float* g3  = (const float*)d_in[16];
    const float* be3 = (const float*)d_in[17];
    const float* Wlin = (const float*)d_in[18];
    const float* blin = (const float*)d_in[19];
    float* out = (float*)d_out;

    cudaFuncSetAttribute(gemm_mma, cudaFuncAttributeMaxDynamicSharedMemorySize, GEMM_SMEM);

    const int mblocks = (NN + 127) / 128;          // 391
    const int gblocks = mblocks * 2;
    const int gwarps  = (NN * 32 + 255) / 256;

    // ----- prologue + layer-1 GEMM (ncu capture slot = 4th launch) -----
    convert_w_all_k<<<(WTOT + 255) / 256, 256>>>(W1l, W1r, W2l, W2r, W3l, W3r);
    conv_x_k<<<(NN * IN_DIM / 4 + 255) / 256, 256>>>(x);
    zero_deg_k<<<(NN + 255) / 256, 256>>>();
    gemm_mma<<<gblocks, 256, GEMM_SMEM>>>(NN, IN_DIM, WOFF1);                // profiled

    // CSR build
    hist_k<<<(NE + 255) / 256, 256>>>(dst);
    alloc_off_k<<<(NN + 255) / 256, 256>>>();
    fill_k<<<(NE + 255) / 256, 256>>>(src, dst);

    // ----- layer 1 tail -----
    gather_k<<<gwarps, 256>>>(b1);
    bn_stats_k<<<256, 128>>>();
    bn_norm_k<<<512, 128>>>(g1, be1);

    // ----- layer 2 -----
    gemm_mma<<<gblocks, 256, GEMM_SMEM>>>(NN, HID, WOFF2);     // block 0 zeroes stats
    gather_k<<<gwarps, 256>>>(b2);
    bn_stats_k<<<256, 128>>>();
    bn_norm_k<<<512, 128>>>(g2, be2);

    // ----- layer 3 -----
    gemm_mma<<<gblocks, 256, GEMM_SMEM>>>(NN, HID, WOFF3);     // block 0 zeroes stats
    gather_k<<<gwarps, 256>>>(b3);
    bn_stats_k<<<256, 128>>>();
    bn_pool_k<<<(NN + POOL_CHUNK - 1) / POOL_CHUNK, 128>>>(batch, g3, be3);

    // ----- head -----
    final_linear_k<<<NG, HID>>>(Wlin, blin, out);
}